// round 1
// baseline (speedup 1.0000x reference)
#include <cuda_runtime.h>
#include <cuda_bf16.h>

// Net: x[B,2] -> fc1(9) -> ELU -> 19 x (fc 9x9 -> ELU) -> fc(2) -> log_softmax
// B = 2,097,152. fp32 throughout using packed f32x2 math (2 batch rows per lane).

#define THREADS 128
#define NP 2   // row-pairs per thread (each pair = 2 batch rows packed in f32x2)

static const int B_ROWS      = 2097152;
static const int NPAIR       = B_ROWS / 2;          // 1,048,576 f32x2 "pairs"
static const int TOT_THREADS = NPAIR / NP;          // 524,288
static const int NBLOCK      = TOT_THREADS / THREADS; // 4096

typedef unsigned long long u64;

// shared-memory weight layout (all duplicated {w,w} as u64)
#define OFF_W1   0      // 18  : W1[j][k] at j*2+k
#define OFF_B1   18     // 9
#define OFF_MW   27     // 19*81 : layer l, j*9+k
#define OFF_MB   1566   // 19*9
#define OFF_W21  1737   // 18 : W21[o][k] at o*9+k
#define OFF_B21  1755   // 2
#define SW_TOT   1757

__device__ __forceinline__ u64 pk2(float lo, float hi) {
    u64 r; asm("mov.b64 %0,{%1,%2};" : "=l"(r) : "f"(lo), "f"(hi)); return r;
}
__device__ __forceinline__ void upk2(float& lo, float& hi, u64 v) {
    asm("mov.b64 {%0,%1},%2;" : "=f"(lo), "=f"(hi) : "l"(v));
}
__device__ __forceinline__ u64 ffma2(u64 a, u64 b, u64 c) {
    u64 d; asm("fma.rn.f32x2 %0,%1,%2,%3;" : "=l"(d) : "l"(a), "l"(b), "l"(c)); return d;
}

// packed ELU: elu(x) = x>0 ? x : exp(x)-1   (exact fp32, exp via MUFU.EX2)
__device__ __forceinline__ u64 elu2(u64 v) {
    float lo, hi; upk2(lo, hi, v);
    float elo = __expf(lo) - 1.0f;
    float ehi = __expf(hi) - 1.0f;
    float rlo = lo > 0.0f ? lo : elo;
    float rhi = hi > 0.0f ? hi : ehi;
    return pk2(rlo, rhi);
}

// log_softmax over 2 logits
__device__ __forceinline__ void lsm2(float l0, float l1, float& o0, float& o1) {
    float m   = fmaxf(l0, l1);
    float t   = __expf(-fabsf(l0 - l1));
    float lse = m + log1pf(t);
    o0 = l0 - lse;
    o1 = l1 - lse;
}

__global__ void __launch_bounds__(THREADS)
mlp_kernel(const float* __restrict__ x,
           const float* __restrict__ W1,  const float* __restrict__ b1,
           const float* __restrict__ Wm,  const float* __restrict__ bm,
           const float* __restrict__ W21, const float* __restrict__ b21,
           float* __restrict__ out)
{
    __shared__ u64 sw[SW_TOT];
    const int t = threadIdx.x;

    // Stage all weights into shared, duplicated into both f32x2 halves.
    for (int i = t; i < 18;   i += THREADS) sw[OFF_W1  + i] = pk2(W1[i],  W1[i]);
    for (int i = t; i < 9;    i += THREADS) sw[OFF_B1  + i] = pk2(b1[i],  b1[i]);
    for (int i = t; i < 1539; i += THREADS) sw[OFF_MW  + i] = pk2(Wm[i],  Wm[i]);
    for (int i = t; i < 171;  i += THREADS) sw[OFF_MB  + i] = pk2(bm[i],  bm[i]);
    for (int i = t; i < 18;   i += THREADS) sw[OFF_W21 + i] = pk2(W21[i], W21[i]);
    for (int i = t; i < 2;    i += THREADS) sw[OFF_B21 + i] = pk2(b21[i], b21[i]);
    __syncthreads();

    const int gtid = blockIdx.x * THREADS + t;

    // Load inputs: one float4 per pair = rows (2p, 2p+1), 2 features each.
    float4 xin[NP];
    int    pidx[NP];
#pragma unroll
    for (int p = 0; p < NP; p++) {
        pidx[p] = gtid + p * TOT_THREADS;          // strided -> coalesced
        xin[p]  = reinterpret_cast<const float4*>(x)[pidx[p]];
    }

    u64 h[NP][9];

    // ---- fc1 + ELU ----
#pragma unroll
    for (int p = 0; p < NP; p++) {
        u64 x0 = pk2(xin[p].x, xin[p].z);   // feature 0 of row A / row B
        u64 x1 = pk2(xin[p].y, xin[p].w);   // feature 1
#pragma unroll
        for (int j = 0; j < 9; j++) {
            u64 acc = ffma2(sw[OFF_W1 + j * 2 + 0], x0, sw[OFF_B1 + j]);
            acc     = ffma2(sw[OFF_W1 + j * 2 + 1], x1, acc);
            h[p][j] = elu2(acc);
        }
    }

    // ---- 19 middle layers (keep the layer loop rolled for I$) ----
#pragma unroll 1
    for (int l = 0; l < 19; l++) {
        const u64* wl = &sw[OFF_MW + l * 81];
        const u64* bl = &sw[OFF_MB + l * 9];
        u64 g[NP][9];
#pragma unroll
        for (int j = 0; j < 9; j++) {
            u64 acc[NP];
#pragma unroll
            for (int p = 0; p < NP; p++) acc[p] = bl[j];
#pragma unroll
            for (int k = 0; k < 9; k++) {
                u64 w = wl[j * 9 + k];
#pragma unroll
                for (int p = 0; p < NP; p++) acc[p] = ffma2(w, h[p][k], acc[p]);
            }
#pragma unroll
            for (int p = 0; p < NP; p++) g[p][j] = elu2(acc[p]);
        }
#pragma unroll
        for (int p = 0; p < NP; p++)
#pragma unroll
            for (int j = 0; j < 9; j++) h[p][j] = g[p][j];
    }

    // ---- output layer + log_softmax ----
#pragma unroll
    for (int p = 0; p < NP; p++) {
        u64 a0 = sw[OFF_B21 + 0];
        u64 a1 = sw[OFF_B21 + 1];
#pragma unroll
        for (int k = 0; k < 9; k++) {
            a0 = ffma2(sw[OFF_W21 + k],     h[p][k], a0);
            a1 = ffma2(sw[OFF_W21 + 9 + k], h[p][k], a1);
        }
        float l0A, l0B, l1A, l1B;
        upk2(l0A, l0B, a0);   // logit0: row A (lo), row B (hi)
        upk2(l1A, l1B, a1);

        float4 o;
        lsm2(l0A, l1A, o.x, o.y);   // row A: out[2p][0], out[2p][1]
        lsm2(l0B, l1B, o.z, o.w);   // row B
        reinterpret_cast<float4*>(out)[pidx[p]] = o;
    }
}

extern "C" void kernel_launch(void* const* d_in, const int* in_sizes, int n_in,
                              void* d_out, int out_size)
{
    const float* x   = (const float*)d_in[0];
    const float* W1  = (const float*)d_in[1];
    const float* b1  = (const float*)d_in[2];
    const float* Wm  = (const float*)d_in[3];
    const float* bm  = (const float*)d_in[4];
    const float* W21 = (const float*)d_in[5];
    const float* b21 = (const float*)d_in[6];
    float*       out = (float*)d_out;

    mlp_kernel<<<NBLOCK, THREADS>>>(x, W1, b1, Wm, bm, W21, b21, out);
}

// round 2
// speedup vs baseline: 1.3018x; 1.3018x over previous
#include <cuda_runtime.h>
#include <cuda_bf16.h>

// Net: x[B,2] -> fc1(9) -> ELU -> 19 x (fc 9x9 -> ELU) -> fc(2) -> log_softmax
// fp32 packed f32x2 math (2 batch rows per lane), scale-domain ELU:
// activations stored as a = log2(e)*elu(z); mid weights unchanged, biases *= log2e,
// W1,b1 *= log2e, W21 *= 1/log2e.

#define THREADS 128
#define NP 2   // f32x2 row-pairs per thread (each pair = 2 batch rows)

static const int B_ROWS      = 2097152;
static const int NPAIR       = B_ROWS / 2;            // 1,048,576
static const int TOT_THREADS = NPAIR / NP;            // 524,288
static const int NBLOCK      = TOT_THREADS / THREADS; // 4096

typedef unsigned long long u64;

#define L2E  1.4426950408889634f
#define IL2E 0.6931471805599453f

// shared layout in u64 units (rows padded to 10 for LDS.128 alignment)
#define OFF_MW   0                   // 19 * 9 * 10 = 1710 ; w[l][j][k] at l*90 + j*10 + k
#define OFF_MB   1710                // 19 * 10 = 190      ; b[l][j]    at l*10 + j   (scaled L2E)
#define OFF_W1   1900                // 18 : W1[j][k] at j*2+k (scaled L2E)
#define OFF_B1   1918                // 9  (scaled L2E)
#define OFF_W21  1928                // 18 : W21[o][k] at o*9+k (scaled 1/L2E)
#define OFF_B21  1946                // 2
#define SW_TOT   1948

__device__ __forceinline__ u64 pk2(float lo, float hi) {
    u64 r; asm("mov.b64 %0,{%1,%2};" : "=l"(r) : "f"(lo), "f"(hi)); return r;
}
__device__ __forceinline__ void upk2(float& lo, float& hi, u64 v) {
    asm("mov.b64 {%0,%1},%2;" : "=f"(lo), "=f"(hi) : "l"(v));
}
__device__ __forceinline__ u64 ffma2(u64 a, u64 b, u64 c) {
    u64 d; asm("fma.rn.f32x2 %0,%1,%2,%3;" : "=l"(d) : "l"(a), "l"(b), "l"(c)); return d;
}
__device__ __forceinline__ float ex2(float x) {
    float r; asm("ex2.approx.ftz.f32 %0, %1;" : "=f"(r) : "f"(x)); return r;
}

// scale-domain packed ELU: in/out are a = log2e * z domain.
// out = max(a, fma(EX2(min(a,0)), L2E, -L2E))
__device__ __forceinline__ u64 elu2s(u64 v) {
    float lo, hi; upk2(lo, hi, v);
    float elo = ex2(fminf(lo, 0.0f));
    float ehi = ex2(fminf(hi, 0.0f));
    float rlo = fmaxf(lo, fmaf(elo, L2E, -L2E));
    float rhi = fmaxf(hi, fmaf(ehi, L2E, -L2E));
    return pk2(rlo, rhi);
}

// log_softmax over 2 logits
__device__ __forceinline__ void lsm2(float l0, float l1, float& o0, float& o1) {
    float m   = fmaxf(l0, l1);
    float t   = __expf(-fabsf(l0 - l1));
    float lse = m + log1pf(t);
    o0 = l0 - lse;
    o1 = l1 - lse;
}

// one 9x9 mid layer + scale-domain ELU, in -> out
__device__ __forceinline__ void mid_layer(const u64* __restrict__ wl,
                                          const u64* __restrict__ bl,
                                          u64 (&in)[NP][9], u64 (&out)[NP][9])
{
    // bias row: 5 shared loads (4x LDS.128 + 1x LDS.64)
    ulonglong2 b01 = *reinterpret_cast<const ulonglong2*>(bl + 0);
    ulonglong2 b23 = *reinterpret_cast<const ulonglong2*>(bl + 2);
    ulonglong2 b45 = *reinterpret_cast<const ulonglong2*>(bl + 4);
    ulonglong2 b67 = *reinterpret_cast<const ulonglong2*>(bl + 6);
    u64 b8 = bl[8];
    u64 bias[9] = {b01.x, b01.y, b23.x, b23.y, b45.x, b45.y, b67.x, b67.y, b8};

#pragma unroll
    for (int j = 0; j < 9; j++) {
        const u64* wr = wl + j * 10;
        ulonglong2 w01 = *reinterpret_cast<const ulonglong2*>(wr + 0);
        ulonglong2 w23 = *reinterpret_cast<const ulonglong2*>(wr + 2);
        ulonglong2 w45 = *reinterpret_cast<const ulonglong2*>(wr + 4);
        ulonglong2 w67 = *reinterpret_cast<const ulonglong2*>(wr + 6);
        u64 w8 = wr[8];
        u64 w[9] = {w01.x, w01.y, w23.x, w23.y, w45.x, w45.y, w67.x, w67.y, w8};

        u64 acc[NP];
#pragma unroll
        for (int p = 0; p < NP; p++) acc[p] = bias[j];
#pragma unroll
        for (int k = 0; k < 9; k++) {
#pragma unroll
            for (int p = 0; p < NP; p++) acc[p] = ffma2(w[k], in[p][k], acc[p]);
        }
#pragma unroll
        for (int p = 0; p < NP; p++) out[p][j] = elu2s(acc[p]);
    }
}

__global__ void __launch_bounds__(THREADS)
mlp_kernel(const float* __restrict__ x,
           const float* __restrict__ W1,  const float* __restrict__ b1,
           const float* __restrict__ Wm,  const float* __restrict__ bm,
           const float* __restrict__ W21, const float* __restrict__ b21,
           float* __restrict__ out)
{
    __shared__ __align__(16) u64 sw[SW_TOT];
    const int t = threadIdx.x;

    // Stage weights into shared, duplicated into both f32x2 halves, scaled per plan.
    for (int i = t; i < 19 * 81; i += THREADS) {
        int l = i / 81, r = i % 81;
        int j = r / 9,  k = r % 9;
        float v = Wm[i];
        sw[OFF_MW + l * 90 + j * 10 + k] = pk2(v, v);   // mid W unscaled
    }
    for (int i = t; i < 19 * 9; i += THREADS) {
        int l = i / 9, j = i % 9;
        float v = bm[i] * L2E;
        sw[OFF_MB + l * 10 + j] = pk2(v, v);
    }
    for (int i = t; i < 18; i += THREADS) { float v = W1[i] * L2E;   sw[OFF_W1 + i]  = pk2(v, v); }
    for (int i = t; i < 9;  i += THREADS) { float v = b1[i] * L2E;   sw[OFF_B1 + i]  = pk2(v, v); }
    for (int i = t; i < 18; i += THREADS) { float v = W21[i] * IL2E; sw[OFF_W21 + i] = pk2(v, v); }
    for (int i = t; i < 2;  i += THREADS) { float v = b21[i];        sw[OFF_B21 + i] = pk2(v, v); }
    __syncthreads();

    const int gtid = blockIdx.x * THREADS + t;

    float4 xin[NP];
    int    pidx[NP];
#pragma unroll
    for (int p = 0; p < NP; p++) {
        pidx[p] = gtid + p * TOT_THREADS;
        xin[p]  = reinterpret_cast<const float4*>(x)[pidx[p]];
    }

    u64 h[NP][9], g[NP][9];

    // ---- fc1 (pre-scaled by L2E) + ELU ----
#pragma unroll
    for (int p = 0; p < NP; p++) {
        u64 x0 = pk2(xin[p].x, xin[p].z);
        u64 x1 = pk2(xin[p].y, xin[p].w);
#pragma unroll
        for (int j = 0; j < 9; j++) {
            u64 acc = ffma2(sw[OFF_W1 + j * 2 + 0], x0, sw[OFF_B1 + j]);
            acc     = ffma2(sw[OFF_W1 + j * 2 + 1], x1, acc);
            h[p][j] = elu2s(acc);
        }
    }

    // ---- 19 mid layers: 9 x (h->g, g->h) + final h->g ----
#pragma unroll 1
    for (int l = 0; l < 9; l++) {
        mid_layer(&sw[OFF_MW + (2 * l)     * 90], &sw[OFF_MB + (2 * l)     * 10], h, g);
        mid_layer(&sw[OFF_MW + (2 * l + 1) * 90], &sw[OFF_MB + (2 * l + 1) * 10], g, h);
    }
    mid_layer(&sw[OFF_MW + 18 * 90], &sw[OFF_MB + 18 * 10], h, g);

    // ---- output layer (W21 pre-scaled 1/L2E) + log_softmax ----
#pragma unroll
    for (int p = 0; p < NP; p++) {
        u64 a0 = sw[OFF_B21 + 0];
        u64 a1 = sw[OFF_B21 + 1];
#pragma unroll
        for (int k = 0; k < 9; k++) {
            a0 = ffma2(sw[OFF_W21 + k],     g[p][k], a0);
            a1 = ffma2(sw[OFF_W21 + 9 + k], g[p][k], a1);
        }
        float l0A, l0B, l1A, l1B;
        upk2(l0A, l0B, a0);
        upk2(l1A, l1B, a1);

        float4 o;
        lsm2(l0A, l1A, o.x, o.y);
        lsm2(l0B, l1B, o.z, o.w);
        reinterpret_cast<float4*>(out)[pidx[p]] = o;
    }
}

extern "C" void kernel_launch(void* const* d_in, const int* in_sizes, int n_in,
                              void* d_out, int out_size)
{
    const float* x   = (const float*)d_in[0];
    const float* W1  = (const float*)d_in[1];
    const float* b1  = (const float*)d_in[2];
    const float* Wm  = (const float*)d_in[3];
    const float* bm  = (const float*)d_in[4];
    const float* W21 = (const float*)d_in[5];
    const float* b21 = (const float*)d_in[6];
    float*       out = (float*)d_out;

    mlp_kernel<<<NBLOCK, THREADS>>>(x, W1, b1, Wm, bm, W21, b21, out);
}